// round 1
// baseline (speedup 1.0000x reference)
#include <cuda_runtime.h>

#define B_TOT  65536
#define NATTR  8
#define NVALS  128
#define ROWS   8          // batch rows per block
#define NBLK   (B_TOT / ROWS)

__device__ double g_loss;
__device__ int    g_acc;
__device__ int    g_acc_or;

__global__ void dl2_init_kernel() {
    g_loss   = 0.0;
    g_acc    = 0;
    g_acc_or = 0;
}

__global__ __launch_bounds__(256, 8)
void dl2_main_kernel(const int* __restrict__ sender,
                     const float* __restrict__ xin) {
    const int wid  = threadIdx.x >> 5;   // attribute index 0..7
    const int lane = threadIdx.x & 31;
    const int b0   = blockIdx.x * ROWS;

    __shared__ float warp_loss[NATTR];
    __shared__ int   match_cnt[ROWS];
    if (threadIdx.x < ROWS) match_cnt[threadIdx.x] = 0;
    __syncthreads();

    float lsum = 0.0f;

    #pragma unroll
    for (int r = 0; r < ROWS; ++r) {
        const int b = b0 + r;
        const float4* row =
            (const float4*)(xin + (size_t)b * (NATTR * NVALS) + wid * NVALS);
        float4 v = row[lane];                 // 16B per lane, coalesced 512B/warp
        int tgt = sender[b * NATTR + wid];    // uniform broadcast within warp

        float vv[4] = {v.x, v.y, v.z, v.w};
        float bestv = vv[0];
        int   besti = lane * 4;
        #pragma unroll
        for (int j = 0; j < 4; ++j) {
            float xv  = vv[j];
            int   col = lane * 4 + j;
            float t   = (col == tgt) ? 1.0f : 0.0f;
            // numerically-stable BCE-with-logits term:
            // max(x,0) - x*t + log1p(exp(-|x|))
            lsum += fmaxf(xv, 0.0f) - xv * t + log1pf(__expf(-fabsf(xv)));
            if (j > 0 && xv > bestv) { bestv = xv; besti = col; }  // strict > keeps lowest idx
        }

        // warp argmax (lowest-index tie-break, matching jnp.argmax)
        #pragma unroll
        for (int off = 16; off; off >>= 1) {
            float ov = __shfl_xor_sync(0xffffffffu, bestv, off);
            int   oi = __shfl_xor_sync(0xffffffffu, besti, off);
            if (ov > bestv || (ov == bestv && oi < besti)) { bestv = ov; besti = oi; }
        }
        if (lane == 0 && besti == tgt) atomicAdd(&match_cnt[r], 1);
    }

    // warp loss reduction
    #pragma unroll
    for (int off = 16; off; off >>= 1)
        lsum += __shfl_xor_sync(0xffffffffu, lsum, off);
    if (lane == 0) warp_loss[wid] = lsum;
    __syncthreads();

    if (threadIdx.x == 0) {
        float bl = 0.0f;
        #pragma unroll
        for (int w = 0; w < NATTR; ++w) bl += warp_loss[w];
        int acc = 0, acc_or = 0;
        #pragma unroll
        for (int r = 0; r < ROWS; ++r) {
            acc_or += match_cnt[r];
            acc    += (match_cnt[r] == NATTR) ? 1 : 0;
        }
        atomicAdd(&g_loss, (double)bl);
        atomicAdd(&g_acc, acc);
        atomicAdd(&g_acc_or, acc_or);
    }
}

__global__ void dl2_finalize_kernel(float* __restrict__ out) {
    out[0] = (float)(g_loss / ((double)B_TOT * NATTR * NVALS));
    out[1] = (float)g_acc    / (float)B_TOT;
    out[2] = (float)g_acc_or / (float)(B_TOT * NATTR);
}

extern "C" void kernel_launch(void* const* d_in, const int* in_sizes, int n_in,
                              void* d_out, int out_size) {
    // Identify inputs by element count (robust to metadata ordering).
    const int*   sender = nullptr;
    const float* xin    = nullptr;
    for (int i = 0; i < n_in; ++i) {
        if (in_sizes[i] == B_TOT * NATTR)         sender = (const int*)d_in[i];
        else if (in_sizes[i] == B_TOT * NATTR * NVALS) xin = (const float*)d_in[i];
    }

    dl2_init_kernel<<<1, 1>>>();
    dl2_main_kernel<<<NBLK, 256>>>(sender, xin);
    dl2_finalize_kernel<<<1, 1>>>((float*)d_out);
}

// round 3
// speedup vs baseline: 2.1782x; 2.1782x over previous
#include <cuda_runtime.h>

#define B_TOT  65536
#define NATTR  8
#define NVALS  128
#define ROWS   8          // batch rows per block
#define NBLK   (B_TOT / ROWS)   // 8192

// Per-block partials. Fully overwritten by dl2_main every run (no init needed).
__device__ float g_ploss[NBLK];
__device__ int   g_pacc[NBLK];   // (acc_all & 0xFF) | (acc_or << 8)

__global__ __launch_bounds__(256)
void dl2_main(const int* __restrict__ sender,
              const float* __restrict__ xin) {
    const int wid  = threadIdx.x >> 5;   // attribute 0..7 (one warp per attr)
    const int lane = threadIdx.x & 31;
    const int b0   = blockIdx.x * ROWS;

    __shared__ float warp_loss[NATTR];
    __shared__ int   warp_match[NATTR];  // bit r set if attr wid matched row r

    float lsum    = 0.0f;
    int   matchbm = 0;

    #pragma unroll
    for (int r = 0; r < ROWS; ++r) {
        const int b = b0 + r;
        const float4* row =
            (const float4*)(xin + (size_t)b * (NATTR * NVALS) + wid * NVALS);
        float4 v  = __ldg(row + lane);               // coalesced 512B/warp
        int   tgt = __ldg(sender + b * NATTR + wid); // uniform broadcast load

        // ---- BCE-with-logits, target-free part: max(x,0) + log(1+exp(-|x|))
        // __expf/__logf are single-MUFU fast paths; 1+e is in (1,2] so LG2 is
        // well-conditioned — log1p edge-case handling not needed here.
        lsum += fmaxf(v.x, 0.f) + fmaxf(v.y, 0.f) + fmaxf(v.z, 0.f) + fmaxf(v.w, 0.f);
        lsum += __logf(1.f + __expf(-fabsf(v.x)));
        lsum += __logf(1.f + __expf(-fabsf(v.y)));
        lsum += __logf(1.f + __expf(-fabsf(v.z)));
        lsum += __logf(1.f + __expf(-fabsf(v.w)));

        // ---- value-only row max (no index tracking)
        float bv = fmaxf(fmaxf(v.x, v.y), fmaxf(v.z, v.w));
        #pragma unroll
        for (int off = 16; off; off >>= 1)
            bv = fmaxf(bv, __shfl_xor_sync(0xffffffffu, bv, off));

        // ---- fetch x[tgt] (uniform tgt): select component, shuffle from owner lane
        int   jm   = tgt & 3;
        float cand = (jm == 0) ? v.x : (jm == 1) ? v.y : (jm == 2) ? v.z : v.w;
        float xtgt = __shfl_sync(0xffffffffu, cand, tgt >> 2);

        if (lane == 0) {
            lsum -= xtgt;                 // the -x*t term, once per (b, attr)
            // argmax==tgt  <=>  x[tgt] equals the row max (ties measure-zero)
            if (xtgt == bv) matchbm |= (1 << r);
        }
    }

    // warp loss reduction (once per block, not per row)
    #pragma unroll
    for (int off = 16; off; off >>= 1)
        lsum += __shfl_xor_sync(0xffffffffu, lsum, off);

    if (lane == 0) { warp_loss[wid] = lsum; warp_match[wid] = matchbm; }
    __syncthreads();

    if (threadIdx.x == 0) {
        float bl   = 0.0f;
        int   andm = 0xFF, orcnt = 0;
        #pragma unroll
        for (int w = 0; w < NATTR; ++w) {
            bl    += warp_loss[w];
            andm  &= warp_match[w];
            orcnt += __popc(warp_match[w]);
        }
        g_ploss[blockIdx.x] = bl;
        g_pacc[blockIdx.x]  = __popc(andm) | (orcnt << 8);
    }
}

__global__ __launch_bounds__(256)
void dl2_finalize(float* __restrict__ out) {
    __shared__ double sl[256];
    __shared__ int    sa[256], so[256];
    const int t = threadIdx.x;

    double l = 0.0;
    int a = 0, o = 0;
    for (int i = t; i < NBLK; i += 256) {
        l += (double)g_ploss[i];
        int p = g_pacc[i];
        a += p & 0xFF;
        o += p >> 8;
    }
    sl[t] = l; sa[t] = a; so[t] = o;
    __syncthreads();
    for (int s = 128; s; s >>= 1) {
        if (t < s) { sl[t] += sl[t + s]; sa[t] += sa[t + s]; so[t] += so[t + s]; }
        __syncthreads();
    }
    if (t == 0) {
        out[0] = (float)(sl[0] / ((double)B_TOT * NATTR * NVALS));
        out[1] = (float)sa[0] / (float)B_TOT;
        out[2] = (float)so[0] / (float)(B_TOT * NATTR);
    }
}

extern "C" void kernel_launch(void* const* d_in, const int* in_sizes, int n_in,
                              void* d_out, int out_size) {
    const int*   sender = nullptr;
    const float* xin    = nullptr;
    for (int i = 0; i < n_in; ++i) {
        if (in_sizes[i] == B_TOT * NATTR)              sender = (const int*)d_in[i];
        else if (in_sizes[i] == B_TOT * NATTR * NVALS) xin    = (const float*)d_in[i];
    }
    dl2_main<<<NBLK, 256>>>(sender, xin);
    dl2_finalize<<<1, 256>>>((float*)d_out);
}